// round 4
// baseline (speedup 1.0000x reference)
#include <cuda_runtime.h>
#include <math.h>

#define NN 50000
#define EE 800000
#define ET (EE + NN)

// -------- static device scratch (no allocations allowed) --------
__device__ float d_buf1[(size_t)NN * 256];   // [XL | XR] layer 1
__device__ float d_H[(size_t)NN * 128];      // elu output of layer 1
__device__ float d_buf2[(size_t)NN * 128];   // [HL | HR] layer 2
__device__ int   d_deg[NN];
__device__ int   d_cur[NN];
__device__ int   d_rowptr[NN];
__device__ int   d_incl[NN];
__device__ int   d_bsums[256];
__device__ int   d_boffs[256];
__device__ int   d_csrsrc[ET];

// -------- CSR build --------
__global__ void k_zero() {
    int i = blockIdx.x * blockDim.x + threadIdx.x;
    if (i < NN) { d_deg[i] = 0; d_cur[i] = 0; }
}

__global__ void k_count(const int* __restrict__ ei) {
    int e = blockIdx.x * blockDim.x + threadIdx.x;
    if (e >= ET) return;
    int dst = (e < EE) ? ei[EE + e] : (e - EE);
    atomicAdd(&d_deg[dst], 1);
}

__global__ void k_scan1() {
    __shared__ int s[256];
    int tid = threadIdx.x;
    int i = blockIdx.x * 256 + tid;
    int v = (i < NN) ? d_deg[i] : 0;
    s[tid] = v; __syncthreads();
    for (int off = 1; off < 256; off <<= 1) {
        int t = (tid >= off) ? s[tid - off] : 0;
        __syncthreads();
        s[tid] += t;
        __syncthreads();
    }
    if (i < NN) d_incl[i] = s[tid];
    if (tid == 255) d_bsums[blockIdx.x] = s[255];
}

__global__ void k_scan2(int nb) {
    __shared__ int s[256];
    int tid = threadIdx.x;
    int v = (tid < nb) ? d_bsums[tid] : 0;
    s[tid] = v; __syncthreads();
    for (int off = 1; off < 256; off <<= 1) {
        int t = (tid >= off) ? s[tid - off] : 0;
        __syncthreads();
        s[tid] += t;
        __syncthreads();
    }
    if (tid < nb) d_boffs[tid] = s[tid] - v;  // exclusive
}

__global__ void k_scan3() {
    int i = blockIdx.x * 256 + threadIdx.x;
    if (i < NN) d_rowptr[i] = d_incl[i] - d_deg[i] + d_boffs[blockIdx.x];
}

__global__ void k_scatter(const int* __restrict__ ei) {
    int e = blockIdx.x * blockDim.x + threadIdx.x;
    if (e >= ET) return;
    int src, dst;
    if (e < EE) { src = ei[e]; dst = ei[EE + e]; }
    else        { src = e - EE; dst = src; }
    int pos = d_rowptr[dst] + atomicAdd(&d_cur[dst], 1);
    d_csrsrc[pos] = src;
}

// -------- SGEMM: C[n x 2*mB] = A[n x 128] @ [B0 | B1] (each 128 x mB) --------
// 64x64 output tile, 256 threads, each thread 4x4. K=128 fully resident for A,
// B streamed in two 64-deep k slabs (48KB static smem total).
__global__ void k_gemm128(const float* __restrict__ A, const float* __restrict__ B0,
                          const float* __restrict__ B1, float* __restrict__ C,
                          int n, int mB) {
    __shared__ float As[128 * 64];  // As[k*64 + r]
    __shared__ float Bs[64 * 64];   // Bs[kk*64 + c]
    const int t = threadIdx.x;
    const int row0 = blockIdx.x * 64;
    const int cb = blockIdx.y * 64;
    const int matIdx = cb / mB;
    const float* __restrict__ B = matIdx ? B1 : B0;
    const int col0 = cb - matIdx * mB;
    const int mC = 2 * mB;

    {   // load A tile transposed
        int r = t & 63, kg = t >> 6;
        bool valid = (row0 + r) < n;
        const float* Ar = A + (size_t)(row0 + r) * 128;
#pragma unroll
        for (int it = 0; it < 8; ++it) {
            int k = (it * 4 + kg) * 4;
            float4 a = valid ? *(const float4*)(Ar + k) : make_float4(0.f, 0.f, 0.f, 0.f);
            As[(k + 0) * 64 + r] = a.x;
            As[(k + 1) * 64 + r] = a.y;
            As[(k + 2) * 64 + r] = a.z;
            As[(k + 3) * 64 + r] = a.w;
        }
    }

    const int tx = t & 15, ty = t >> 4;
    float acc[4][4];
#pragma unroll
    for (int i = 0; i < 4; ++i)
#pragma unroll
        for (int j = 0; j < 4; ++j) acc[i][j] = 0.f;

    for (int kh = 0; kh < 2; ++kh) {
        __syncthreads();  // guards As (first iter) and Bs reuse (second iter)
#pragma unroll
        for (int i = 0; i < 4; ++i) {
            int idx4 = t + 256 * i;
            int kk = idx4 >> 4;
            int c = (idx4 & 15) << 2;
            *(float4*)&Bs[kk * 64 + c] =
                *(const float4*)(B + (size_t)(kh * 64 + kk) * mB + col0 + c);
        }
        __syncthreads();
#pragma unroll 8
        for (int kk = 0; kk < 64; ++kk) {
            float4 b4 = *(const float4*)&Bs[kk * 64 + tx * 4];
            float4 a4 = *(const float4*)&As[(kh * 64 + kk) * 64 + ty * 4];
            acc[0][0] += a4.x * b4.x; acc[0][1] += a4.x * b4.y; acc[0][2] += a4.x * b4.z; acc[0][3] += a4.x * b4.w;
            acc[1][0] += a4.y * b4.x; acc[1][1] += a4.y * b4.y; acc[1][2] += a4.y * b4.z; acc[1][3] += a4.y * b4.w;
            acc[2][0] += a4.z * b4.x; acc[2][1] += a4.z * b4.y; acc[2][2] += a4.z * b4.z; acc[2][3] += a4.z * b4.w;
            acc[3][0] += a4.w * b4.x; acc[3][1] += a4.w * b4.y; acc[3][2] += a4.w * b4.z; acc[3][3] += a4.w * b4.w;
        }
    }
#pragma unroll
    for (int i = 0; i < 4; ++i) {
        int r = row0 + ty * 4 + i;
        if (r < n)
            *(float4*)&C[(size_t)r * mC + cb + tx * 4] =
                make_float4(acc[i][0], acc[i][1], acc[i][2], acc[i][3]);
    }
}

// -------- Layer 1: warp per dst node, online softmax over 8 heads x 16 ch --------
__global__ void k_gat1(const float* __restrict__ att1, const float* __restrict__ b1) {
    int warp = (blockIdx.x * blockDim.x + threadIdx.x) >> 5;
    int lane = threadIdx.x & 31;
    if (warp >= NN) return;
    int dst = warp;
    // lane l owns channels 4l..4l+3 of the 128 = (h=l>>2, c=(l*4)&15..)
    float4 xr = *(const float4*)&d_buf1[(size_t)dst * 256 + 128 + lane * 4];
    float4 at = *(const float4*)&att1[lane * 4];
    int beg = d_rowptr[dst];
    int cnt = d_deg[dst];
    float m = -1e30f, den = 0.f;
    float4 acc = make_float4(0.f, 0.f, 0.f, 0.f);
    for (int i = 0; i < cnt; ++i) {
        int s = d_csrsrc[beg + i];
        float4 xl = *(const float4*)&d_buf1[(size_t)s * 256 + lane * 4];
        float e0 = xl.x + xr.x; e0 = e0 > 0.f ? e0 : 0.2f * e0;
        float e1 = xl.y + xr.y; e1 = e1 > 0.f ? e1 : 0.2f * e1;
        float e2 = xl.z + xr.z; e2 = e2 > 0.f ? e2 : 0.2f * e2;
        float e3 = xl.w + xr.w; e3 = e3 > 0.f ? e3 : 0.2f * e3;
        float p = e0 * at.x + e1 * at.y + e2 * at.z + e3 * at.w;
        p += __shfl_xor_sync(0xffffffffu, p, 1);
        p += __shfl_xor_sync(0xffffffffu, p, 2);   // logit of this lane's head
        float nm = fmaxf(m, p);
        float sc = __expf(m - nm);
        float w  = __expf(p - nm);
        den = den * sc + w;
        acc.x = acc.x * sc + w * xl.x;
        acc.y = acc.y * sc + w * xl.y;
        acc.z = acc.z * sc + w * xl.z;
        acc.w = acc.w * sc + w * xl.w;
        m = nm;
    }
    float inv = 1.f / den;
    float4 bb = *(const float4*)&b1[lane * 4];
    float v0 = acc.x * inv + bb.x; v0 = v0 > 0.f ? v0 : expm1f(v0);
    float v1 = acc.y * inv + bb.y; v1 = v1 > 0.f ? v1 : expm1f(v1);
    float v2 = acc.z * inv + bb.z; v2 = v2 > 0.f ? v2 : expm1f(v2);
    float v3 = acc.w * inv + bb.w; v3 = v3 > 0.f ? v3 : expm1f(v3);
    *(float4*)&d_H[(size_t)dst * 128 + lane * 4] = make_float4(v0, v1, v2, v3);
}

// -------- Layer 2: warp per dst node, single head of 64 ch + log_softmax --------
__global__ void k_gat2(const float* __restrict__ att2, const float* __restrict__ b2,
                       float* __restrict__ out) {
    int warp = (blockIdx.x * blockDim.x + threadIdx.x) >> 5;
    int lane = threadIdx.x & 31;
    if (warp >= NN) return;
    int dst = warp;
    float2 hr = *(const float2*)&d_buf2[(size_t)dst * 128 + 64 + lane * 2];
    float2 a2 = *(const float2*)&att2[lane * 2];
    int beg = d_rowptr[dst];
    int cnt = d_deg[dst];
    float m = -1e30f, den = 0.f;
    float2 acc = make_float2(0.f, 0.f);
    for (int i = 0; i < cnt; ++i) {
        int s = d_csrsrc[beg + i];
        float2 hl = *(const float2*)&d_buf2[(size_t)s * 128 + lane * 2];
        float e0 = hl.x + hr.x; e0 = e0 > 0.f ? e0 : 0.2f * e0;
        float e1 = hl.y + hr.y; e1 = e1 > 0.f ? e1 : 0.2f * e1;
        float p = e0 * a2.x + e1 * a2.y;
#pragma unroll
        for (int off = 16; off >= 1; off >>= 1)
            p += __shfl_xor_sync(0xffffffffu, p, off);
        float nm = fmaxf(m, p);
        float sc = __expf(m - nm);
        float w  = __expf(p - nm);
        den = den * sc + w;
        acc.x = acc.x * sc + w * hl.x;
        acc.y = acc.y * sc + w * hl.y;
        m = nm;
    }
    float inv = 1.f / den;
    float o0 = acc.x * inv + b2[lane * 2];
    float o1 = acc.y * inv + b2[lane * 2 + 1];
    // log_softmax over 64 channels (2 per lane)
    float mx = fmaxf(o0, o1);
#pragma unroll
    for (int off = 16; off >= 1; off >>= 1)
        mx = fmaxf(mx, __shfl_xor_sync(0xffffffffu, mx, off));
    float se = __expf(o0 - mx) + __expf(o1 - mx);
#pragma unroll
    for (int off = 16; off >= 1; off >>= 1)
        se += __shfl_xor_sync(0xffffffffu, se, off);
    float lse = mx + logf(se);
    out[(size_t)dst * 64 + lane * 2]     = o0 - lse;
    out[(size_t)dst * 64 + lane * 2 + 1] = o1 - lse;
}

// -------- launch --------
extern "C" void kernel_launch(void* const* d_in, const int* in_sizes, int n_in,
                              void* d_out, int out_size) {
    const float* x    = (const float*)d_in[0];
    const int*   ei   = (const int*)d_in[1];
    const float* Wl1  = (const float*)d_in[2];
    const float* Wr1  = (const float*)d_in[3];
    const float* att1 = (const float*)d_in[4];
    const float* b1   = (const float*)d_in[5];
    const float* Wl2  = (const float*)d_in[6];
    const float* Wr2  = (const float*)d_in[7];
    const float* att2 = (const float*)d_in[8];
    const float* b2   = (const float*)d_in[9];
    float* out = (float*)d_out;

    float *pBuf1 = nullptr, *pH = nullptr, *pBuf2 = nullptr;
    cudaGetSymbolAddress((void**)&pBuf1, d_buf1);
    cudaGetSymbolAddress((void**)&pH, d_H);
    cudaGetSymbolAddress((void**)&pBuf2, d_buf2);

    const int nb_nodes = (NN + 255) / 256;   // 196
    const int nb_edges = (ET + 255) / 256;

    // CSR build (identical graph used by both layers)
    k_zero<<<nb_nodes, 256>>>();
    k_count<<<nb_edges, 256>>>(ei);
    k_scan1<<<nb_nodes, 256>>>();
    k_scan2<<<1, 256>>>(nb_nodes);
    k_scan3<<<nb_nodes, 256>>>();
    k_scatter<<<nb_edges, 256>>>(ei);

    // Layer 1
    dim3 g1((NN + 63) / 64, 4);
    k_gemm128<<<g1, 256>>>(x, Wl1, Wr1, pBuf1, NN, 128);
    k_gat1<<<(NN + 7) / 8, 256>>>(att1, b1);

    // Layer 2
    dim3 g2((NN + 63) / 64, 2);
    k_gemm128<<<g2, 256>>>(pH, Wl2, Wr2, pBuf2, NN, 64);
    k_gat2<<<(NN + 7) / 8, 256>>>(att2, b2, out);
}

// round 5
// speedup vs baseline: 1.3535x; 1.3535x over previous
#include <cuda_runtime.h>
#include <math.h>

#define NN 50000
#define EE 800000
#define ET (EE + NN)

// -------- static device scratch (no allocations allowed) --------
__device__ float d_buf1[(size_t)NN * 256];   // [XL | XR] layer 1
__device__ float d_H[(size_t)NN * 128];      // elu output of layer 1
__device__ float d_buf2[(size_t)NN * 128];   // [HL | HR] layer 2
__device__ float d_Bt1[256 * 128];           // transposed [Wl1|Wr1]: Bt[c][k]
__device__ float d_Bt2[128 * 128];           // transposed [Wl2|Wr2]
__device__ int   d_deg[NN];
__device__ int   d_cur[NN];
__device__ int   d_rowptr[NN];
__device__ int   d_incl[NN];
__device__ int   d_bsums[256];
__device__ int   d_boffs[256];
__device__ int   d_csrsrc[ET];

// -------- CSR build --------
__global__ void k_zero() {
    int i = blockIdx.x * blockDim.x + threadIdx.x;
    if (i < NN) { d_deg[i] = 0; d_cur[i] = 0; }
}

__global__ void k_count(const int* __restrict__ ei) {
    int e = blockIdx.x * blockDim.x + threadIdx.x;
    if (e >= ET) return;
    int dst = (e < EE) ? ei[EE + e] : (e - EE);
    atomicAdd(&d_deg[dst], 1);
}

__global__ void k_scan1() {
    __shared__ int s[256];
    int tid = threadIdx.x;
    int i = blockIdx.x * 256 + tid;
    int v = (i < NN) ? d_deg[i] : 0;
    s[tid] = v; __syncthreads();
    for (int off = 1; off < 256; off <<= 1) {
        int t = (tid >= off) ? s[tid - off] : 0;
        __syncthreads();
        s[tid] += t;
        __syncthreads();
    }
    if (i < NN) d_incl[i] = s[tid];
    if (tid == 255) d_bsums[blockIdx.x] = s[255];
}

__global__ void k_scan2(int nb) {
    __shared__ int s[256];
    int tid = threadIdx.x;
    int v = (tid < nb) ? d_bsums[tid] : 0;
    s[tid] = v; __syncthreads();
    for (int off = 1; off < 256; off <<= 1) {
        int t = (tid >= off) ? s[tid - off] : 0;
        __syncthreads();
        s[tid] += t;
        __syncthreads();
    }
    if (tid < nb) d_boffs[tid] = s[tid] - v;  // exclusive
}

__global__ void k_scan3() {
    int i = blockIdx.x * 256 + threadIdx.x;
    if (i < NN) d_rowptr[i] = d_incl[i] - d_deg[i] + d_boffs[blockIdx.x];
}

__global__ void k_scatter(const int* __restrict__ ei) {
    int e = blockIdx.x * blockDim.x + threadIdx.x;
    if (e >= ET) return;
    int src, dst;
    if (e < EE) { src = ei[e]; dst = ei[EE + e]; }
    else        { src = e - EE; dst = src; }
    int pos = d_rowptr[dst] + atomicAdd(&d_cur[dst], 1);
    d_csrsrc[pos] = src;
}

// -------- weight transpose: Bt[c][k] = [Wl|Wr][k][c] --------
__global__ void k_transW(const float* __restrict__ Wl, const float* __restrict__ Wr,
                         float* __restrict__ Bt, int mB) {
    int idx = blockIdx.x * 256 + threadIdx.x;
    int total = 2 * mB * 128;
    if (idx >= total) return;
    int c = idx >> 7, k = idx & 127;
    Bt[idx] = (c < mB) ? Wl[k * mB + c] : Wr[k * mB + (c - mB)];
}

// -------- tf32 tensor-core GEMM --------
// C[n x mC] = A[n x 128] @ Bt^T,  Bt is [mC][128] row-major (pre-transposed weights).
// Block tile 128x64, 256 threads = 8 warps in 4(m) x 2(n) grid, warp tile 32x32.
// K staged in 32-deep slabs; fp32 -> tf32 converted once at smem-store time.
#define GPAD 36   // slab row stride in words: bank = (4*row + k) mod 32 -> conflict-free frags

__device__ __forceinline__ unsigned f2tf(float f) {
    unsigned r;
    asm("cvt.rna.tf32.f32 %0, %1;" : "=r"(r) : "f"(f));
    return r;
}

__device__ __forceinline__ void mma8(float* d, const unsigned* a, const unsigned* b) {
    asm("mma.sync.aligned.m16n8k8.row.col.f32.tf32.tf32.f32 "
        "{%0,%1,%2,%3}, {%4,%5,%6,%7}, {%8,%9}, {%0,%1,%2,%3};"
        : "+f"(d[0]), "+f"(d[1]), "+f"(d[2]), "+f"(d[3])
        : "r"(a[0]), "r"(a[1]), "r"(a[2]), "r"(a[3]), "r"(b[0]), "r"(b[1]));
}

__global__ void k_gemm_tc(const float* __restrict__ A, const float* __restrict__ Bt,
                          float* __restrict__ C, int n, int mC) {
    __shared__ unsigned As[128 * GPAD];  // As[r][k], tf32 bits
    __shared__ unsigned Bs[64 * GPAD];   // Bs[c][k], tf32 bits
    const int t    = threadIdx.x;
    const int lane = t & 31;
    const int w    = t >> 5;
    const int wr   = w & 3;        // warp m index (rows wr*32)
    const int wc   = w >> 2;       // warp n index (cols wc*32)
    const int gid  = lane >> 2;    // 0..7
    const int tig  = lane & 3;     // 0..3
    const int row0 = blockIdx.x * 128;
    const int col0 = blockIdx.y * 64;

    float acc[2][4][4];
#pragma unroll
    for (int mt = 0; mt < 2; ++mt)
#pragma unroll
        for (int nt = 0; nt < 4; ++nt)
#pragma unroll
            for (int i = 0; i < 4; ++i) acc[mt][nt][i] = 0.f;

    for (int ks = 0; ks < 128; ks += 32) {
        __syncthreads();
        {   // A slab: 128 rows x 32 k = 1024 float4, 4 per thread
            int r  = t >> 1;
            int kb = (t & 1) * 16;
            bool valid = (row0 + r) < n;
            const float* Ar = A + (size_t)(row0 + r) * 128 + ks + kb;
#pragma unroll
            for (int j = 0; j < 4; ++j) {
                float4 v = valid ? *(const float4*)(Ar + j * 4)
                                 : make_float4(0.f, 0.f, 0.f, 0.f);
                *(uint4*)&As[r * GPAD + kb + j * 4] =
                    make_uint4(f2tf(v.x), f2tf(v.y), f2tf(v.z), f2tf(v.w));
            }
        }
        {   // B slab: 64 cols x 32 k = 512 float4, 2 per thread
            int c  = t >> 2;
            int kb = (t & 3) * 8;
            const float* Br = Bt + (size_t)(col0 + c) * 128 + ks + kb;
#pragma unroll
            for (int j = 0; j < 2; ++j) {
                float4 v = *(const float4*)(Br + j * 4);
                *(uint4*)&Bs[c * GPAD + kb + j * 4] =
                    make_uint4(f2tf(v.x), f2tf(v.y), f2tf(v.z), f2tf(v.w));
            }
        }
        __syncthreads();
#pragma unroll
        for (int kk = 0; kk < 32; kk += 8) {
            unsigned a[2][4], b[4][2];
#pragma unroll
            for (int mt = 0; mt < 2; ++mt) {
                int r = wr * 32 + mt * 16 + gid;
                a[mt][0] = As[r * GPAD + kk + tig];
                a[mt][1] = As[(r + 8) * GPAD + kk + tig];
                a[mt][2] = As[r * GPAD + kk + tig + 4];
                a[mt][3] = As[(r + 8) * GPAD + kk + tig + 4];
            }
#pragma unroll
            for (int nt = 0; nt < 4; ++nt) {
                int c = wc * 32 + nt * 8 + gid;
                b[nt][0] = Bs[c * GPAD + kk + tig];
                b[nt][1] = Bs[c * GPAD + kk + tig + 4];
            }
#pragma unroll
            for (int mt = 0; mt < 2; ++mt)
#pragma unroll
                for (int nt = 0; nt < 4; ++nt)
                    mma8(acc[mt][nt], a[mt], b[nt]);
        }
    }

    // epilogue: d0,d1 -> (row, 2*tig), d2,d3 -> (row+8, 2*tig)
#pragma unroll
    for (int mt = 0; mt < 2; ++mt) {
        int r = row0 + wr * 32 + mt * 16 + gid;
        int cbase = col0 + wc * 32 + tig * 2;
#pragma unroll
        for (int nt = 0; nt < 4; ++nt) {
            if (r < n)
                *(float2*)&C[(size_t)r * mC + cbase + nt * 8] =
                    make_float2(acc[mt][nt][0], acc[mt][nt][1]);
            if (r + 8 < n)
                *(float2*)&C[(size_t)(r + 8) * mC + cbase + nt * 8] =
                    make_float2(acc[mt][nt][2], acc[mt][nt][3]);
        }
    }
}

// -------- Layer 1: warp per dst node, online softmax over 8 heads x 16 ch --------
__global__ void k_gat1(const float* __restrict__ att1, const float* __restrict__ b1) {
    int warp = (blockIdx.x * blockDim.x + threadIdx.x) >> 5;
    int lane = threadIdx.x & 31;
    if (warp >= NN) return;
    int dst = warp;
    float4 xr = *(const float4*)&d_buf1[(size_t)dst * 256 + 128 + lane * 4];
    float4 at = *(const float4*)&att1[lane * 4];
    int beg = d_rowptr[dst];
    int cnt = d_deg[dst];
    float m = -1e30f, den = 0.f;
    float4 acc = make_float4(0.f, 0.f, 0.f, 0.f);
    for (int i = 0; i < cnt; ++i) {
        int s = d_csrsrc[beg + i];
        float4 xl = *(const float4*)&d_buf1[(size_t)s * 256 + lane * 4];
        float e0 = xl.x + xr.x; e0 = e0 > 0.f ? e0 : 0.2f * e0;
        float e1 = xl.y + xr.y; e1 = e1 > 0.f ? e1 : 0.2f * e1;
        float e2 = xl.z + xr.z; e2 = e2 > 0.f ? e2 : 0.2f * e2;
        float e3 = xl.w + xr.w; e3 = e3 > 0.f ? e3 : 0.2f * e3;
        float p = e0 * at.x + e1 * at.y + e2 * at.z + e3 * at.w;
        p += __shfl_xor_sync(0xffffffffu, p, 1);
        p += __shfl_xor_sync(0xffffffffu, p, 2);   // logit of this lane's head
        float nm = fmaxf(m, p);
        float sc = __expf(m - nm);
        float w  = __expf(p - nm);
        den = den * sc + w;
        acc.x = acc.x * sc + w * xl.x;
        acc.y = acc.y * sc + w * xl.y;
        acc.z = acc.z * sc + w * xl.z;
        acc.w = acc.w * sc + w * xl.w;
        m = nm;
    }
    float inv = 1.f / den;
    float4 bb = *(const float4*)&b1[lane * 4];
    float v0 = acc.x * inv + bb.x; v0 = v0 > 0.f ? v0 : expm1f(v0);
    float v1 = acc.y * inv + bb.y; v1 = v1 > 0.f ? v1 : expm1f(v1);
    float v2 = acc.z * inv + bb.z; v2 = v2 > 0.f ? v2 : expm1f(v2);
    float v3 = acc.w * inv + bb.w; v3 = v3 > 0.f ? v3 : expm1f(v3);
    *(float4*)&d_H[(size_t)dst * 128 + lane * 4] = make_float4(v0, v1, v2, v3);
}

// -------- Layer 2: warp per dst node, single head of 64 ch + log_softmax --------
__global__ void k_gat2(const float* __restrict__ att2, const float* __restrict__ b2,
                       float* __restrict__ out) {
    int warp = (blockIdx.x * blockDim.x + threadIdx.x) >> 5;
    int lane = threadIdx.x & 31;
    if (warp >= NN) return;
    int dst = warp;
    float2 hr = *(const float2*)&d_buf2[(size_t)dst * 128 + 64 + lane * 2];
    float2 a2 = *(const float2*)&att2[lane * 2];
    int beg = d_rowptr[dst];
    int cnt = d_deg[dst];
    float m = -1e30f, den = 0.f;
    float2 acc = make_float2(0.f, 0.f);
    for (int i = 0; i < cnt; ++i) {
        int s = d_csrsrc[beg + i];
        float2 hl = *(const float2*)&d_buf2[(size_t)s * 128 + lane * 2];
        float e0 = hl.x + hr.x; e0 = e0 > 0.f ? e0 : 0.2f * e0;
        float e1 = hl.y + hr.y; e1 = e1 > 0.f ? e1 : 0.2f * e1;
        float p = e0 * a2.x + e1 * a2.y;
#pragma unroll
        for (int off = 16; off >= 1; off >>= 1)
            p += __shfl_xor_sync(0xffffffffu, p, off);
        float nm = fmaxf(m, p);
        float sc = __expf(m - nm);
        float w  = __expf(p - nm);
        den = den * sc + w;
        acc.x = acc.x * sc + w * hl.x;
        acc.y = acc.y * sc + w * hl.y;
        m = nm;
    }
    float inv = 1.f / den;
    float o0 = acc.x * inv + b2[lane * 2];
    float o1 = acc.y * inv + b2[lane * 2 + 1];
    float mx = fmaxf(o0, o1);
#pragma unroll
    for (int off = 16; off >= 1; off >>= 1)
        mx = fmaxf(mx, __shfl_xor_sync(0xffffffffu, mx, off));
    float se = __expf(o0 - mx) + __expf(o1 - mx);
#pragma unroll
    for (int off = 16; off >= 1; off >>= 1)
        se += __shfl_xor_sync(0xffffffffu, se, off);
    float lse = mx + logf(se);
    out[(size_t)dst * 64 + lane * 2]     = o0 - lse;
    out[(size_t)dst * 64 + lane * 2 + 1] = o1 - lse;
}

// -------- launch --------
extern "C" void kernel_launch(void* const* d_in, const int* in_sizes, int n_in,
                              void* d_out, int out_size) {
    const float* x    = (const float*)d_in[0];
    const int*   ei   = (const int*)d_in[1];
    const float* Wl1  = (const float*)d_in[2];
    const float* Wr1  = (const float*)d_in[3];
    const float* att1 = (const float*)d_in[4];
    const float* b1   = (const float*)d_in[5];
    const float* Wl2  = (const float*)d_in[6];
    const float* Wr2  = (const float*)d_in[7];
    const float* att2 = (const float*)d_in[8];
    const float* b2   = (const float*)d_in[9];
    float* out = (float*)d_out;

    float *pBuf1 = nullptr, *pH = nullptr, *pBuf2 = nullptr, *pBt1 = nullptr, *pBt2 = nullptr;
    cudaGetSymbolAddress((void**)&pBuf1, d_buf1);
    cudaGetSymbolAddress((void**)&pH, d_H);
    cudaGetSymbolAddress((void**)&pBuf2, d_buf2);
    cudaGetSymbolAddress((void**)&pBt1, d_Bt1);
    cudaGetSymbolAddress((void**)&pBt2, d_Bt2);

    const int nb_nodes = (NN + 255) / 256;   // 196
    const int nb_edges = (ET + 255) / 256;

    // CSR build (same graph used by both layers)
    k_zero<<<nb_nodes, 256>>>();
    k_count<<<nb_edges, 256>>>(ei);
    k_scan1<<<nb_nodes, 256>>>();
    k_scan2<<<1, 256>>>(nb_nodes);
    k_scan3<<<nb_nodes, 256>>>();
    k_scatter<<<nb_edges, 256>>>(ei);

    // weight transposes (tiny)
    k_transW<<<(256 * 128 + 255) / 256, 256>>>(Wl1, Wr1, pBt1, 128);
    k_transW<<<(128 * 128 + 255) / 256, 256>>>(Wl2, Wr2, pBt2, 64);

    // Layer 1: [XL|XR] = x @ [Wl1|Wr1]   (C is 50000 x 256)
    dim3 g1((NN + 127) / 128, 4);
    k_gemm_tc<<<g1, 256>>>(x, pBt1, pBuf1, NN, 256);
    k_gat1<<<(NN + 7) / 8, 256>>>(att1, b1);

    // Layer 2: [HL|HR] = H @ [Wl2|Wr2]   (C is 50000 x 128)
    dim3 g2((NN + 127) / 128, 2);
    k_gemm_tc<<<g2, 256>>>(pH, pBt2, pBuf2, NN, 128);
    k_gat2<<<(NN + 7) / 8, 256>>>(att2, b2, out);
}